// round 1
// baseline (speedup 1.0000x reference)
#include <cuda_runtime.h>
#include <cuda_bf16.h>

// Problem constants (fixed by setup_inputs)
#define BATCH   4
#define SEQ     512
#define DMODEL  4096
#define NHQ     32
#define NHKV    8
#define HDIM    128
#define TCACHE  1024
#define TTOT    1536            // start_pos + S
#define TMAXC   2048            // cache T_MAX
#define MROWS   (BATCH*SEQ)     // 2048

// ---------------- scratch (no allocations allowed) ----------------
__device__ float g_q[(size_t)MROWS * DMODEL];          // 2048 x 4096
__device__ float g_k[(size_t)MROWS * (NHKV*HDIM)];     // 2048 x 1024
__device__ float g_v[(size_t)MROWS * (NHKV*HDIM)];     // 2048 x 1024
__device__ float g_o[(size_t)MROWS * DMODEL];          // 2048 x 4096

// ---------------- SGEMM: C[M,N] = A[M,K] * B[N,K]^T (NT, fp32) ----------------
// 128x128 tile, BK=16, 256 threads, 8x8 per thread.
#define SG_LDS 132
__global__ __launch_bounds__(256) void sgemm_nt(
    const float* __restrict__ A, const float* __restrict__ Bm,
    float* __restrict__ C, int M, int N, int K)
{
    __shared__ float As[16 * SG_LDS];
    __shared__ float Bs[16 * SG_LDS];
    const int tid = threadIdx.x;
    const int bx = blockIdx.x, by = blockIdx.y;
    const float* Ab = A + (size_t)by * 128 * K;
    const float* Bb = Bm + (size_t)bx * 128 * K;
    const int lrow = tid >> 2;            // 0..63
    const int lcol = (tid & 3) << 2;      // 0,4,8,12
    const int ty = tid >> 4, tx = tid & 15;
    float acc[8][8];
#pragma unroll
    for (int i = 0; i < 8; i++)
#pragma unroll
        for (int j = 0; j < 8; j++) acc[i][j] = 0.f;

    for (int k0 = 0; k0 < K; k0 += 16) {
#pragma unroll
        for (int it = 0; it < 2; ++it) {
            int r = lrow + it * 64;
            float4 av = *(const float4*)(Ab + (size_t)r * K + k0 + lcol);
            As[(lcol + 0) * SG_LDS + r] = av.x;
            As[(lcol + 1) * SG_LDS + r] = av.y;
            As[(lcol + 2) * SG_LDS + r] = av.z;
            As[(lcol + 3) * SG_LDS + r] = av.w;
            float4 bv = *(const float4*)(Bb + (size_t)r * K + k0 + lcol);
            Bs[(lcol + 0) * SG_LDS + r] = bv.x;
            Bs[(lcol + 1) * SG_LDS + r] = bv.y;
            Bs[(lcol + 2) * SG_LDS + r] = bv.z;
            Bs[(lcol + 3) * SG_LDS + r] = bv.w;
        }
        __syncthreads();
#pragma unroll
        for (int kk = 0; kk < 16; ++kk) {
            float a[8], b[8];
            *(float4*)(a)     = *(const float4*)&As[kk * SG_LDS + ty * 8];
            *(float4*)(a + 4) = *(const float4*)&As[kk * SG_LDS + ty * 8 + 4];
            *(float4*)(b)     = *(const float4*)&Bs[kk * SG_LDS + tx * 8];
            *(float4*)(b + 4) = *(const float4*)&Bs[kk * SG_LDS + tx * 8 + 4];
#pragma unroll
            for (int i = 0; i < 8; i++)
#pragma unroll
                for (int j = 0; j < 8; j++) acc[i][j] += a[i] * b[j];
        }
        __syncthreads();
    }
#pragma unroll
    for (int i = 0; i < 8; i++) {
        float* Crow = C + (size_t)(by * 128 + ty * 8 + i) * N + bx * 128 + tx * 8;
        float4 v0 = {acc[i][0], acc[i][1], acc[i][2], acc[i][3]};
        float4 v1 = {acc[i][4], acc[i][5], acc[i][6], acc[i][7]};
        *(float4*)(Crow)     = v0;
        *(float4*)(Crow + 4) = v1;
    }
}

// ---------------- RoPE (in-place on g_q, g_k) ----------------
__global__ void rope_kernel(const float* __restrict__ fc, const float* __restrict__ fs)
{
    const int QP = MROWS * NHQ * 64;       // q pairs
    const int KP = MROWS * NHKV * 64;      // k pairs
    int idx = blockIdx.x * blockDim.x + threadIdx.x;
    if (idx >= QP + KP) return;
    float* buf; int row, hp, stride;
    if (idx < QP) { buf = g_q; row = idx / (NHQ * 64);  hp = idx % (NHQ * 64);  stride = DMODEL; }
    else { int j = idx - QP; buf = g_k; row = j / (NHKV * 64); hp = j % (NHKV * 64); stride = NHKV * HDIM; }
    const int i = hp & 63;
    const int s = row & (SEQ - 1);
    const float c  = fc[s * 64 + i];
    const float sn = fs[s * 64 + i];
    const size_t base = (size_t)row * stride + (size_t)hp * 2;  // hp*2 = head*128 + 2*i
    const float xr = buf[base], xi = buf[base + 1];
    buf[base]     = xr * c - xi * sn;
    buf[base + 1] = xr * sn + xi * c;
}

// ---------------- Flash attention: block = (b, h, 64-query tile) ----------------
// smem floats: Qs 64x128 | KV: K^T 128x65 (reused as V 64x128) | S 64x65 | m,l,a 64ea | red 256
#define ATT_SMEM_FLOATS (8192 + 8320 + 4160 + 64*3 + 256)
__global__ __launch_bounds__(256) void attn_kernel(
    const float* __restrict__ qb, const float* __restrict__ kb, const float* __restrict__ vb,
    const float* __restrict__ ck, const float* __restrict__ cv,
    const float* __restrict__ masks, float* __restrict__ ob)
{
    extern __shared__ float sm[];
    float* Qs  = sm;                 // [64][128]
    float* KV  = Qs + 8192;          // K^T [128][65] then V [64][128]
    float* Sm  = KV + 8320;          // [64][65]
    float* m_s = Sm + 4160;
    float* l_s = m_s + 64;
    float* a_s = l_s + 64;
    float* red = a_s + 64;           // [4][64]

    const int tid = threadIdx.x;
    const int b = blockIdx.z, h = blockIdx.y, g = h >> 2;
    const int s0 = blockIdx.x * 64;
    const float scale = 0.08838834764831845f;   // 1/sqrt(128)

    // load Q tile, pre-scaled
    for (int i = tid; i < 64 * 128 / 4; i += 256) {
        int r = i >> 5, c = (i & 31) << 2;
        float4 v = *(const float4*)(qb + ((size_t)(b * SEQ + s0 + r)) * DMODEL + h * HDIM + c);
        v.x *= scale; v.y *= scale; v.z *= scale; v.w *= scale;
        *(float4*)(Qs + r * 128 + c) = v;
    }
    if (tid < 64) { m_s[tid] = -1e30f; l_s[tid] = 0.f; }
    float acc[4][8];
#pragma unroll
    for (int i = 0; i < 4; i++)
#pragma unroll
        for (int j = 0; j < 8; j++) acc[i][j] = 0.f;
    const int ty = tid >> 4, tx = tid & 15;
    const int row = tid & 63, grp = tid >> 6;
    __syncthreads();

    for (int t0 = 0; t0 < TTOT; t0 += 64) {
        // load K tile transposed: KV[d][t], stride 65
        for (int i = tid; i < 64 * 128 / 4; i += 256) {
            int t = i >> 5, c = (i & 31) << 2;
            int tg = t0 + t;
            const float* src = (tg < TCACHE)
                ? ck + ((((size_t)b * TMAXC + tg) * NHKV + g) << 7) + c
                : kb + ((size_t)(b * SEQ + tg - TCACHE) << 10) + g * HDIM + c;
            float4 v = *(const float4*)src;
            KV[(c + 0) * 65 + t] = v.x;
            KV[(c + 1) * 65 + t] = v.y;
            KV[(c + 2) * 65 + t] = v.z;
            KV[(c + 3) * 65 + t] = v.w;
        }
        __syncthreads();

        // scores: thread computes 4 (rows) x 4 (cols)
        float sc[4][4];
#pragma unroll
        for (int i = 0; i < 4; i++)
#pragma unroll
            for (int j = 0; j < 4; j++) sc[i][j] = 0.f;
#pragma unroll 4
        for (int d = 0; d < 128; ++d) {
            float qv[4], kv[4];
#pragma unroll
            for (int i = 0; i < 4; i++) qv[i] = Qs[(ty * 4 + i) * 128 + d];
#pragma unroll
            for (int j = 0; j < 4; j++) kv[j] = KV[d * 65 + tx * 4 + j];
#pragma unroll
            for (int i = 0; i < 4; i++)
#pragma unroll
                for (int j = 0; j < 4; j++) sc[i][j] += qv[i] * kv[j];
        }
#pragma unroll
        for (int i = 0; i < 4; i++)
#pragma unroll
            for (int j = 0; j < 4; j++)
                Sm[(ty * 4 + i) * 65 + tx * 4 + j] =
                    sc[i][j] + masks[(size_t)(s0 + ty * 4 + i) * TTOT + t0 + tx * 4 + j];
        __syncthreads();

        // online softmax: row = tid&63, 4 groups of 16 cols
        float lm = -1e30f;
#pragma unroll
        for (int c = 0; c < 16; c++) lm = fmaxf(lm, Sm[row * 65 + grp * 16 + c]);
        red[grp * 64 + row] = lm;
        __syncthreads();
        if (grp == 0) {
            float mnew = fmaxf(fmaxf(red[row], red[64 + row]), fmaxf(red[128 + row], red[192 + row]));
            float mold = m_s[row];
            mnew = fmaxf(mold, mnew);
            m_s[row] = mnew;
            a_s[row] = __expf(mold - mnew);
        }
        __syncthreads();
        float mnew = m_s[row];
        float lsum = 0.f;
#pragma unroll
        for (int c = 0; c < 16; c++) {
            float e = __expf(Sm[row * 65 + grp * 16 + c] - mnew);
            Sm[row * 65 + grp * 16 + c] = e;
            lsum += e;
        }
        red[grp * 64 + row] = lsum;
        // rescale accumulator (a_s stable since the sync above)
#pragma unroll
        for (int i = 0; i < 4; i++) {
            float al = a_s[ty * 4 + i];
#pragma unroll
            for (int j = 0; j < 8; j++) acc[i][j] *= al;
        }
        __syncthreads();
        if (grp == 0)
            l_s[row] = l_s[row] * a_s[row] + red[row] + red[64 + row] + red[128 + row] + red[192 + row];

        // load V tile (row-major) into KV region
        for (int i = tid; i < 64 * 128 / 4; i += 256) {
            int t = i >> 5, c = (i & 31) << 2;
            int tg = t0 + t;
            const float* src = (tg < TCACHE)
                ? cv + ((((size_t)b * TMAXC + tg) * NHKV + g) << 7) + c
                : vb + ((size_t)(b * SEQ + tg - TCACHE) << 10) + g * HDIM + c;
            *(float4*)(KV + t * 128 + c) = *(const float4*)src;
        }
        __syncthreads();

        // acc += P(64x64) @ V(64x128); thread: 4 rows x 8 cols
#pragma unroll 2
        for (int t = 0; t < 64; ++t) {
            float p[4], vv[8];
#pragma unroll
            for (int i = 0; i < 4; i++) p[i] = Sm[(ty * 4 + i) * 65 + t];
            *(float4*)(vv)     = *(const float4*)(KV + t * 128 + tx * 8);
            *(float4*)(vv + 4) = *(const float4*)(KV + t * 128 + tx * 8 + 4);
#pragma unroll
            for (int i = 0; i < 4; i++)
#pragma unroll
                for (int j = 0; j < 8; j++) acc[i][j] += p[i] * vv[j];
        }
        __syncthreads();
    }

    // epilogue: divide by l, write o_buf[b][s][h*128+d]
#pragma unroll
    for (int i = 0; i < 4; i++) {
        float inv = 1.f / l_s[ty * 4 + i];
        float* dst = ob + ((size_t)(b * SEQ + s0 + ty * 4 + i)) * DMODEL + h * HDIM + tx * 8;
        float4 v0 = {acc[i][0] * inv, acc[i][1] * inv, acc[i][2] * inv, acc[i][3] * inv};
        float4 v1 = {acc[i][4] * inv, acc[i][5] * inv, acc[i][6] * inv, acc[i][7] * inv};
        *(float4*)(dst)     = v0;
        *(float4*)(dst + 4) = v1;
    }
}

// ---------------- launch ----------------
extern "C" void kernel_launch(void* const* d_in, const int* in_sizes, int n_in,
                              void* d_out, int out_size)
{
    const float* x     = (const float*)d_in[0];
    const float* wq    = (const float*)d_in[1];
    const float* wk    = (const float*)d_in[2];
    const float* wv    = (const float*)d_in[3];
    const float* wo    = (const float*)d_in[4];
    const float* fc    = (const float*)d_in[5];
    const float* fs    = (const float*)d_in[6];
    const float* ck    = (const float*)d_in[7];
    const float* cv    = (const float*)d_in[8];
    const float* masks = (const float*)d_in[9];
    float* out = (float*)d_out;

    float *qp, *kp, *vp, *op;
    cudaGetSymbolAddress((void**)&qp, g_q);
    cudaGetSymbolAddress((void**)&kp, g_k);
    cudaGetSymbolAddress((void**)&vp, g_v);
    cudaGetSymbolAddress((void**)&op, g_o);

    const int att_smem = ATT_SMEM_FLOATS * sizeof(float);
    cudaFuncSetAttribute(attn_kernel, cudaFuncAttributeMaxDynamicSharedMemorySize, att_smem);

    // QKV projections
    sgemm_nt<<<dim3(DMODEL / 128, MROWS / 128), 256>>>(x, wq, qp, MROWS, DMODEL, DMODEL);
    sgemm_nt<<<dim3((NHKV * HDIM) / 128, MROWS / 128), 256>>>(x, wk, kp, MROWS, NHKV * HDIM, DMODEL);
    sgemm_nt<<<dim3((NHKV * HDIM) / 128, MROWS / 128), 256>>>(x, wv, vp, MROWS, NHKV * HDIM, DMODEL);

    // RoPE on q and k
    {
        int total = MROWS * (NHQ + NHKV) * 64;
        rope_kernel<<<(total + 255) / 256, 256>>>(fc, fs);
    }

    // attention
    attn_kernel<<<dim3(SEQ / 64, NHQ, BATCH), 256, att_smem>>>(qp, kp, vp, ck, cv, masks, op);

    // output projection -> d_out
    sgemm_nt<<<dim3(DMODEL / 128, MROWS / 128), 256>>>(op, wo, out, MROWS, DMODEL, DMODEL);
}

// round 2
// speedup vs baseline: 1.3846x; 1.3846x over previous
#include <cuda_runtime.h>
#include <cuda_bf16.h>
#include <cstdint>

// Problem constants (fixed by setup_inputs)
#define BATCH   4
#define SEQ     512
#define DMODEL  4096
#define NHQ     32
#define NHKV    8
#define HDIM    128
#define TCACHE  1024
#define TTOT    1536            // start_pos + S
#define TMAXC   2048            // cache T_MAX
#define MROWS   (BATCH*SEQ)     // 2048
#define KVD     (NHKV*HDIM)     // 1024

// ---------------- scratch (no allocations allowed) ----------------
__device__ float g_q[(size_t)MROWS * DMODEL];          // 2048 x 4096 fp32
__device__ float g_k[(size_t)MROWS * KVD];             // 2048 x 1024 fp32
__device__ float g_v[(size_t)MROWS * KVD];             // 2048 x 1024 fp32
__device__ float g_o[(size_t)MROWS * DMODEL];          // 2048 x 4096 fp32 (attn out)

// bf16 hi/lo splits
__device__ __nv_bfloat16 g_xh[(size_t)MROWS * DMODEL];
__device__ __nv_bfloat16 g_xl[(size_t)MROWS * DMODEL];
__device__ __nv_bfloat16 g_wqh[(size_t)DMODEL * DMODEL];
__device__ __nv_bfloat16 g_wql[(size_t)DMODEL * DMODEL];
__device__ __nv_bfloat16 g_wkh[(size_t)KVD * DMODEL];
__device__ __nv_bfloat16 g_wkl[(size_t)KVD * DMODEL];
__device__ __nv_bfloat16 g_wvh[(size_t)KVD * DMODEL];
__device__ __nv_bfloat16 g_wvl[(size_t)KVD * DMODEL];
__device__ __nv_bfloat16 g_woh[(size_t)DMODEL * DMODEL];
__device__ __nv_bfloat16 g_wol[(size_t)DMODEL * DMODEL];
__device__ __nv_bfloat16 g_oh[(size_t)MROWS * DMODEL];
__device__ __nv_bfloat16 g_ol[(size_t)MROWS * DMODEL];

// ---------------- fp32 -> bf16 hi/lo split ----------------
__global__ void split_kernel(const float* __restrict__ src,
                             __nv_bfloat16* __restrict__ hi,
                             __nv_bfloat16* __restrict__ lo, int n4)
{
    int i = blockIdx.x * blockDim.x + threadIdx.x;
    if (i >= n4) return;
    float4 v = ((const float4*)src)[i];
    __nv_bfloat16 h0 = __float2bfloat16(v.x);
    __nv_bfloat16 h1 = __float2bfloat16(v.y);
    __nv_bfloat16 h2 = __float2bfloat16(v.z);
    __nv_bfloat16 h3 = __float2bfloat16(v.w);
    __nv_bfloat162 hA; hA.x = h0; hA.y = h1;
    __nv_bfloat162 hB; hB.x = h2; hB.y = h3;
    __nv_bfloat162 lA, lB;
    lA.x = __float2bfloat16(v.x - __bfloat162float(h0));
    lA.y = __float2bfloat16(v.y - __bfloat162float(h1));
    lB.x = __float2bfloat16(v.z - __bfloat162float(h2));
    lB.y = __float2bfloat16(v.w - __bfloat162float(h3));
    ((__nv_bfloat162*)hi)[i * 2]     = hA;
    ((__nv_bfloat162*)hi)[i * 2 + 1] = hB;
    ((__nv_bfloat162*)lo)[i * 2]     = lA;
    ((__nv_bfloat162*)lo)[i * 2 + 1] = lB;
}

// ---------------- bf16x3 tensor-core GEMM ----------------
// C[M,N] = A[M,K] * B[N,K]^T in fp32-accurate arithmetic via
// sum over segments: Ah*Bh + Ah*Bl + Al*Bh  (effective K' = 3K).
// 128x128 tile, BK=32, 256 threads (8 warps, 2x4), warp tile 64x32,
// mma.sync m16n8k16 bf16, cp.async double buffering.
#define GBK   32
#define GPITCH 40      // halves per smem row (conflict-free: 20 words, odd*4)

__device__ __forceinline__ uint32_t smem_u32(const void* p) {
    return (uint32_t)__cvta_generic_to_shared(p);
}

__global__ __launch_bounds__(256, 2) void gemm3_bf16(
    const __nv_bfloat16* __restrict__ Ah, const __nv_bfloat16* __restrict__ Al,
    const __nv_bfloat16* __restrict__ Bh, const __nv_bfloat16* __restrict__ Bl,
    float* __restrict__ C, int M, int N, int K)
{
    __shared__ __nv_bfloat16 As[2][128 * GPITCH];
    __shared__ __nv_bfloat16 Bs[2][128 * GPITCH];

    const int tid  = threadIdx.x;
    const int bm   = blockIdx.y * 128;
    const int bn   = blockIdx.x * 128;
    const int lane = tid & 31, warp = tid >> 5;
    const int wm   = (warp >> 2) * 64;     // 0,64
    const int wn   = (warp & 3) * 32;      // 0,32,64,96
    const int g    = lane >> 2, t = lane & 3;

    float c[4][4][4];
#pragma unroll
    for (int mi = 0; mi < 4; mi++)
#pragma unroll
        for (int ni = 0; ni < 4; ni++)
#pragma unroll
            for (int r = 0; r < 4; r++) c[mi][ni][r] = 0.f;

    const int NT = (3 * K) / GBK;
    const int lr = tid >> 2;          // 0..63
    const int lc = (tid & 3) * 8;     // 0,8,16,24 (halves)

    auto load_stage = [&](int kt, int buf) {
        int k0  = kt * GBK;
        int seg = k0 / K;                       // 0,1,2
        int ks  = k0 - seg * K;
        const __nv_bfloat16* Asrc = (seg < 2) ? Ah : Al;
        const __nv_bfloat16* Bsrc = (seg == 1) ? Bl : Bh;
#pragma unroll
        for (int it = 0; it < 2; ++it) {
            int r = lr + it * 64;
            uint32_t da = smem_u32(&As[buf][r * GPITCH + lc]);
            const void* sa = Asrc + (size_t)(bm + r) * K + ks + lc;
            asm volatile("cp.async.ca.shared.global [%0], [%1], 16;\n" :: "r"(da), "l"(sa));
            uint32_t db = smem_u32(&Bs[buf][r * GPITCH + lc]);
            const void* sb = Bsrc + (size_t)(bn + r) * K + ks + lc;
            asm volatile("cp.async.ca.shared.global [%0], [%1], 16;\n" :: "r"(db), "l"(sb));
        }
        asm volatile("cp.async.commit_group;\n");
    };

    load_stage(0, 0);

    for (int kt = 0; kt < NT; ++kt) {
        asm volatile("cp.async.wait_group 0;\n");
        __syncthreads();
        if (kt + 1 < NT) load_stage(kt + 1, (kt + 1) & 1);

        const uint32_t* A32 = (const uint32_t*)&As[kt & 1][0];
        const uint32_t* B32 = (const uint32_t*)&Bs[kt & 1][0];
#pragma unroll
        for (int ks8 = 0; ks8 < 16; ks8 += 8) {     // two k16 steps (word offsets)
            uint32_t af[4][4], bfr[4][2];
#pragma unroll
            for (int mi = 0; mi < 4; mi++) {
                int base = (wm + mi * 16 + g) * (GPITCH / 2) + t + ks8;
                af[mi][0] = A32[base];
                af[mi][1] = A32[base + 8 * (GPITCH / 2)];
                af[mi][2] = A32[base + 4];
                af[mi][3] = A32[base + 8 * (GPITCH / 2) + 4];
            }
#pragma unroll
            for (int ni = 0; ni < 4; ni++) {
                int base = (wn + ni * 8 + g) * (GPITCH / 2) + t + ks8;
                bfr[ni][0] = B32[base];
                bfr[ni][1] = B32[base + 4];
            }
#pragma unroll
            for (int mi = 0; mi < 4; mi++)
#pragma unroll
                for (int ni = 0; ni < 4; ni++) {
                    asm volatile(
                        "mma.sync.aligned.m16n8k16.row.col.f32.bf16.bf16.f32 "
                        "{%0,%1,%2,%3}, {%4,%5,%6,%7}, {%8,%9}, {%0,%1,%2,%3};"
                        : "+f"(c[mi][ni][0]), "+f"(c[mi][ni][1]),
                          "+f"(c[mi][ni][2]), "+f"(c[mi][ni][3])
                        : "r"(af[mi][0]), "r"(af[mi][1]), "r"(af[mi][2]), "r"(af[mi][3]),
                          "r"(bfr[ni][0]), "r"(bfr[ni][1]));
                }
        }
        __syncthreads();
    }

    // epilogue: c[mi][ni]: rows wm+mi*16+g (+8), cols wn+ni*8+t*2 (+1)
#pragma unroll
    for (int mi = 0; mi < 4; mi++)
#pragma unroll
        for (int ni = 0; ni < 4; ni++) {
            int row0 = bm + wm + mi * 16 + g;
            int col  = bn + wn + ni * 8 + t * 2;
            float2 v0 = {c[mi][ni][0], c[mi][ni][1]};
            float2 v1 = {c[mi][ni][2], c[mi][ni][3]};
            *(float2*)(C + (size_t)row0 * N + col)       = v0;
            *(float2*)(C + (size_t)(row0 + 8) * N + col) = v1;
        }
}

// ---------------- RoPE (in-place on g_q, g_k) ----------------
__global__ void rope_kernel(const float* __restrict__ fc, const float* __restrict__ fs)
{
    const int QP = MROWS * NHQ * 64;
    const int KP = MROWS * NHKV * 64;
    int idx = blockIdx.x * blockDim.x + threadIdx.x;
    if (idx >= QP + KP) return;
    float* buf; int row, hp, stride;
    if (idx < QP) { buf = g_q; row = idx / (NHQ * 64);  hp = idx % (NHQ * 64);  stride = DMODEL; }
    else { int j = idx - QP; buf = g_k; row = j / (NHKV * 64); hp = j % (NHKV * 64); stride = KVD; }
    const int i = hp & 63;
    const int s = row & (SEQ - 1);
    const float c  = fc[s * 64 + i];
    const float sn = fs[s * 64 + i];
    const size_t base = (size_t)row * stride + (size_t)hp * 2;
    const float xr = buf[base], xi = buf[base + 1];
    buf[base]     = xr * c - xi * sn;
    buf[base + 1] = xr * sn + xi * c;
}

// ---------------- Flash attention (fp32, unchanged from R1) ----------------
#define ATT_SMEM_FLOATS (8192 + 8320 + 4160 + 64*3 + 256)
__global__ __launch_bounds__(256) void attn_kernel(
    const float* __restrict__ qb, const float* __restrict__ kb, const float* __restrict__ vb,
    const float* __restrict__ ck, const float* __restrict__ cv,
    const float* __restrict__ masks, float* __restrict__ ob)
{
    extern __shared__ float sm[];
    float* Qs  = sm;
    float* KV  = Qs + 8192;
    float* Sm  = KV + 8320;
    float* m_s = Sm + 4160;
    float* l_s = m_s + 64;
    float* a_s = l_s + 64;
    float* red = a_s + 64;

    const int tid = threadIdx.x;
    const int b = blockIdx.z, h = blockIdx.y, g = h >> 2;
    const int s0 = blockIdx.x * 64;
    const float scale = 0.08838834764831845f;

    for (int i = tid; i < 64 * 128 / 4; i += 256) {
        int r = i >> 5, c = (i & 31) << 2;
        float4 v = *(const float4*)(qb + ((size_t)(b * SEQ + s0 + r)) * DMODEL + h * HDIM + c);
        v.x *= scale; v.y *= scale; v.z *= scale; v.w *= scale;
        *(float4*)(Qs + r * 128 + c) = v;
    }
    if (tid < 64) { m_s[tid] = -1e30f; l_s[tid] = 0.f; }
    float acc[4][8];
#pragma unroll
    for (int i = 0; i < 4; i++)
#pragma unroll
        for (int j = 0; j < 8; j++) acc[i][j] = 0.f;
    const int ty = tid >> 4, tx = tid & 15;
    const int row = tid & 63, grp = tid >> 6;
    __syncthreads();

    for (int t0 = 0; t0 < TTOT; t0 += 64) {
        for (int i = tid; i < 64 * 128 / 4; i += 256) {
            int t = i >> 5, c = (i & 31) << 2;
            int tg = t0 + t;
            const float* src = (tg < TCACHE)
                ? ck + ((((size_t)b * TMAXC + tg) * NHKV + g) << 7) + c
                : kb + ((size_t)(b * SEQ + tg - TCACHE) << 10) + g * HDIM + c;
            float4 v = *(const float4*)src;
            KV[(c + 0) * 65 + t] = v.x;
            KV[(c + 1) * 65 + t] = v.y;
            KV[(c + 2) * 65 + t] = v.z;
            KV[(c + 3) * 65 + t] = v.w;
        }
        __syncthreads();

        float sc[4][4];
#pragma unroll
        for (int i = 0; i < 4; i++)
#pragma unroll
            for (int j = 0; j < 4; j++) sc[i][j] = 0.f;
#pragma unroll 4
        for (int d = 0; d < 128; ++d) {
            float qv[4], kv[4];
#pragma unroll
            for (int i = 0; i < 4; i++) qv[i] = Qs[(ty * 4 + i) * 128 + d];
#pragma unroll
            for (int j = 0; j < 4; j++) kv[j] = KV[d * 65 + tx * 4 + j];
#pragma unroll
            for (int i = 0; i < 4; i++)
#pragma unroll
                for (int j = 0; j < 4; j++) sc[i][j] += qv[i] * kv[j];
        }
#pragma unroll
        for (int i = 0; i < 4; i++)
#pragma unroll
            for (int j = 0; j < 4; j++)
                Sm[(ty * 4 + i) * 65 + tx * 4 + j] =
                    sc[i][j] + masks[(size_t)(s0 + ty * 4 + i) * TTOT + t0 + tx * 4 + j];
        __syncthreads();

        float lm = -1e30f;
#pragma unroll
        for (int c = 0; c < 16; c++) lm = fmaxf(lm, Sm[row * 65 + grp * 16 + c]);
        red[grp * 64 + row] = lm;
        __syncthreads();
        if (grp == 0) {
            float mnew = fmaxf(fmaxf(red[row], red[64 + row]), fmaxf(red[128 + row], red[192 + row]));
            float mold = m_s[row];
            mnew = fmaxf(mold, mnew);
            m_s[row] = mnew;
            a_s[row] = __expf(mold - mnew);
        }
        __syncthreads();
        float mnew = m_s[row];
        float lsum = 0.f;
#pragma unroll
        for (int c = 0; c < 16; c++) {
            float e = __expf(Sm[row * 65 + grp * 16 + c] - mnew);
            Sm[row * 65 + grp * 16 + c] = e;
            lsum += e;
        }
        red[grp * 64 + row] = lsum;
#pragma unroll
        for (int i = 0; i < 4; i++) {
            float al = a_s[ty * 4 + i];
#pragma unroll
            for (int j = 0; j < 8; j++) acc[i][j] *= al;
        }
        __syncthreads();
        if (grp == 0)
            l_s[row] = l_s[row] * a_s[row] + red[row] + red[64 + row] + red[128 + row] + red[192 + row];

        for (int i = tid; i < 64 * 128 / 4; i += 256) {
            int t = i >> 5, c = (i & 31) << 2;
            int tg = t0 + t;
            const float* src = (tg < TCACHE)
                ? cv + ((((size_t)b * TMAXC + tg) * NHKV + g) << 7) + c
                : vb + ((size_t)(b * SEQ + tg - TCACHE) << 10) + g * HDIM + c;
            *(float4*)(KV + t * 128 + c) = *(const float4*)src;
        }
        __syncthreads();

#pragma unroll 2
        for (int t = 0; t < 64; ++t) {
            float p[4], vv[8];
#pragma unroll
            for (int i = 0; i < 4; i++) p[i] = Sm[(ty * 4 + i) * 65 + t];
            *(float4*)(vv)     = *(const float4*)(KV + t * 128 + tx * 8);
            *(float4*)(vv + 4) = *(const float4*)(KV + t * 128 + tx * 8 + 4);
#pragma unroll
            for (int i = 0; i < 4; i++)
#pragma unroll
                for (int j = 0; j < 8; j++) acc[i][j] += p[i] * vv[j];
        }
        __syncthreads();
    }

#pragma unroll
    for (int i = 0; i < 4; i++) {
        float inv = 1.f / l_s[ty * 4 + i];
        float* dst = ob + ((size_t)(b * SEQ + s0 + ty * 4 + i)) * DMODEL + h * HDIM + tx * 8;
        float4 v0 = {acc[i][0] * inv, acc[i][1] * inv, acc[i][2] * inv, acc[i][3] * inv};
        float4 v1 = {acc[i][4] * inv, acc[i][5] * inv, acc[i][6] * inv, acc[i][7] * inv};
        *(float4*)(dst)     = v0;
        *(float4*)(dst + 4) = v1;
    }
}

// ---------------- launch ----------------
extern "C" void kernel_launch(void* const* d_in, const int* in_sizes, int n_in,
                              void* d_out, int out_size)
{
    const float* x     = (const float*)d_in[0];
    const float* wq    = (const float*)d_in[1];
    const float* wk    = (const float*)d_in[2];
    const float* wv    = (const float*)d_in[3];
    const float* wo    = (const float*)d_in[4];
    const float* fc    = (const float*)d_in[5];
    const float* fs    = (const float*)d_in[6];
    const float* ck    = (const float*)d_in[7];
    const float* cv    = (const float*)d_in[8];
    const float* masks = (const float*)d_in[9];
    float* out = (float*)d_out;

    float *qp, *kp, *vp, *op;
    cudaGetSymbolAddress((void**)&qp, g_q);
    cudaGetSymbolAddress((void**)&kp, g_k);
    cudaGetSymbolAddress((void**)&vp, g_v);
    cudaGetSymbolAddress((void**)&op, g_o);
    __nv_bfloat16 *xh, *xl, *wqh, *wql, *wkh, *wkl, *wvh, *wvl, *woh, *wol, *oh, *ol;
    cudaGetSymbolAddress((void**)&xh, g_xh);   cudaGetSymbolAddress((void**)&xl, g_xl);
    cudaGetSymbolAddress((void**)&wqh, g_wqh); cudaGetSymbolAddress((void**)&wql, g_wql);
    cudaGetSymbolAddress((void**)&wkh, g_wkh); cudaGetSymbolAddress((void**)&wkl, g_wkl);
    cudaGetSymbolAddress((void**)&wvh, g_wvh); cudaGetSymbolAddress((void**)&wvl, g_wvl);
    cudaGetSymbolAddress((void**)&woh, g_woh); cudaGetSymbolAddress((void**)&wol, g_wol);
    cudaGetSymbolAddress((void**)&oh, g_oh);   cudaGetSymbolAddress((void**)&ol, g_ol);

    const int att_smem = ATT_SMEM_FLOATS * sizeof(float);
    cudaFuncSetAttribute(attn_kernel, cudaFuncAttributeMaxDynamicSharedMemorySize, att_smem);

    // split inputs/weights into bf16 hi/lo
    auto launch_split = [&](const float* s, __nv_bfloat16* h, __nv_bfloat16* l, size_t n) {
        int n4 = (int)(n / 4);
        split_kernel<<<(n4 + 255) / 256, 256>>>(s, h, l, n4);
    };
    launch_split(x,  xh,  xl,  (size_t)MROWS * DMODEL);
    launch_split(wq, wqh, wql, (size_t)DMODEL * DMODEL);
    launch_split(wk, wkh, wkl, (size_t)KVD * DMODEL);
    launch_split(wv, wvh, wvl, (size_t)KVD * DMODEL);
    launch_split(wo, woh, wol, (size_t)DMODEL * DMODEL);

    // QKV projections (bf16x3 tensor core)
    gemm3_bf16<<<dim3(DMODEL / 128, MROWS / 128), 256>>>(xh, xl, wqh, wql, qp, MROWS, DMODEL, DMODEL);
    gemm3_bf16<<<dim3(KVD / 128,    MROWS / 128), 256>>>(xh, xl, wkh, wkl, kp, MROWS, KVD, DMODEL);
    gemm3_bf16<<<dim3(KVD / 128,    MROWS / 128), 256>>>(xh, xl, wvh, wvl, vp, MROWS, KVD, DMODEL);

    // RoPE on q and k
    {
        int total = MROWS * (NHQ + NHKV) * 64;
        rope_kernel<<<(total + 255) / 256, 256>>>(fc, fs);
    }

    // attention (fp32)
    attn_kernel<<<dim3(SEQ / 64, NHQ, BATCH), 256, att_smem>>>(qp, kp, vp, ck, cv, masks, op);

    // split attention output, then output projection
    launch_split(op, oh, ol, (size_t)MROWS * DMODEL);
    gemm3_bf16<<<dim3(DMODEL / 128, MROWS / 128), 256>>>(oh, ol, woh, wol, out, MROWS, DMODEL, DMODEL);
}